// round 4
// baseline (speedup 1.0000x reference)
#include <cuda_runtime.h>

// ---------------------------------------------------------------------------
// ArcFace fused kernel set for GB300 (sm_103a)
//   out[0*B*C .. )  : cos            = (feat/|feat|) @ (W/|W|)^T
//   out[1*B*C .. )  : marginal       = 35*cos, with gt column replaced
//   out[2*B*C .. )  : innerproduct   = feat @ W^T
// B=256, D=128, C=100000 (D fixed at 128; B,C derived at runtime)
// ---------------------------------------------------------------------------

static __device__ __constant__ float kCOS_M  = 0.8775825618903728f;   // cos(0.5)
static __device__ __constant__ float kSIN_M  = 0.4794255386042030f;   // sin(0.5)
static __device__ __constant__ float kTHRESH = -0.8775825618903728f;  // -cos(0.5)
#define K_MARGIN 0.5f
#define K_SCALE  35.0f

// scratch: inverse norms (static device arrays — no allocation allowed)
__device__ float g_invnf[1024];
__device__ float g_invnw[100608];

// packed f32x2 helpers (PTX-only path on sm_103a)
#define FFMA2(acc, a, b) \
    asm("fma.rn.f32x2 %0, %1, %2, %0;" : "+l"(acc) : "l"(a), "l"(b))
#define PACKF2(out, lo, hi) \
    asm("mov.b64 %0, {%1, %2};" : "=l"(out) : "f"(lo), "f"(hi))
#define UNPACKF2(lo, hi, in) \
    asm("mov.b64 {%0, %1}, %2;" : "=f"(lo), "=f"(hi) : "l"(in))

// ---------------------------------------------------------------------------
// inverse L2 norms of rows of x [rows, 128]; which==0 -> g_invnf, else g_invnw
// ---------------------------------------------------------------------------
__global__ void norm_kernel(const float* __restrict__ x, int rows, int which) {
    int row = blockIdx.x * blockDim.y + threadIdx.y;
    if (row >= rows) return;
    int lane = threadIdx.x;  // 0..31, 4 floats each -> 128
    float4 v = *reinterpret_cast<const float4*>(x + (size_t)row * 128 + lane * 4);
    float s = v.x * v.x + v.y * v.y + v.z * v.z + v.w * v.w;
#pragma unroll
    for (int o = 16; o > 0; o >>= 1) s += __shfl_xor_sync(0xffffffffu, s, o);
    if (lane == 0) {
        float inv = rsqrtf(s);
        if (which) g_invnw[row] = inv; else g_invnf[row] = inv;
    }
}

// ---------------------------------------------------------------------------
// Tiled GEMM: dot[b][c] = feat[b,:] . W[c,:], then fused epilogue writing
// cos / 35*cos / dot to the three output planes.
// Tile: BM=128 (batch) x BN=128 (classes) x BK=16, 256 threads,
// per-thread 8x8 microtile held as 4 m-pairs x 8 n in packed f32x2 regs.
// ---------------------------------------------------------------------------
__global__ __launch_bounds__(256, 2)
void arcface_gemm(const float* __restrict__ feat, const float* __restrict__ W,
                  float* __restrict__ out, int B, int C) {
    constexpr int BM = 128, BN = 128, BK = 16, D = 128;
    constexpr int NKC = D / BK;  // 8 k-chunks

    __shared__ alignas(16) float As[2][BK][BM + 4];  // [k][m], row 132 floats
    __shared__ alignas(16) float Bs[2][BK][BN + 4];  // [k][c]

    const int tid = threadIdx.x;
    const int tn = tid & 15;        // 0..15 -> n
    const int tm = tid >> 4;        // 0..15 -> m
    const int tn4 = tn * 4;
    const int tm4 = tm * 4;
    const int m0 = blockIdx.y * BM;
    const int c0 = blockIdx.x * BN;

    unsigned long long acc[4][8];   // [m-pair][n], each = packed (f32,f32)
#pragma unroll
    for (int i = 0; i < 4; ++i)
#pragma unroll
        for (int j = 0; j < 8; ++j) acc[i][j] = 0ull;

    float4 aR[2], wR[2];

    // global->reg loaders: tile is 128 rows x 16 k = 512 float4, 2 per thread
    auto loadA = [&](int kk) {
#pragma unroll
        for (int it = 0; it < 2; ++it) {
            int fi = tid + 256 * it;
            int row = fi >> 2, kq = fi & 3;
            int g = m0 + row;
            aR[it] = (g < B)
                ? *reinterpret_cast<const float4*>(feat + (size_t)g * D + kk + kq * 4)
                : make_float4(0.f, 0.f, 0.f, 0.f);
        }
    };
    auto loadW = [&](int kk) {
#pragma unroll
        for (int it = 0; it < 2; ++it) {
            int fi = tid + 256 * it;
            int row = fi >> 2, kq = fi & 3;
            int g = c0 + row;
            wR[it] = (g < C)
                ? *reinterpret_cast<const float4*>(W + (size_t)g * D + kk + kq * 4)
                : make_float4(0.f, 0.f, 0.f, 0.f);
        }
    };
    auto stash = [&](int buf) {
#pragma unroll
        for (int it = 0; it < 2; ++it) {
            int fi = tid + 256 * it;
            int row = fi >> 2, k = (fi & 3) * 4;
            As[buf][k + 0][row] = aR[it].x;
            As[buf][k + 1][row] = aR[it].y;
            As[buf][k + 2][row] = aR[it].z;
            As[buf][k + 3][row] = aR[it].w;
            Bs[buf][k + 0][row] = wR[it].x;
            Bs[buf][k + 1][row] = wR[it].y;
            Bs[buf][k + 2][row] = wR[it].z;
            Bs[buf][k + 3][row] = wR[it].w;
        }
    };

    loadA(0); loadW(0);
    stash(0);
    __syncthreads();

#pragma unroll
    for (int kc = 0; kc < NKC; ++kc) {
        const int cur = kc & 1;
        if (kc + 1 < NKC) { loadA((kc + 1) * BK); loadW((kc + 1) * BK); }

#pragma unroll
        for (int k = 0; k < BK; ++k) {
            // m-pairs read directly as packed 64-bit (no MOVs needed)
            ulonglong2 aA = *reinterpret_cast<const ulonglong2*>(&As[cur][k][tm4]);
            ulonglong2 aB = *reinterpret_cast<const ulonglong2*>(&As[cur][k][64 + tm4]);
            float4 b0 = *reinterpret_cast<const float4*>(&Bs[cur][k][tn4]);
            float4 b1 = *reinterpret_cast<const float4*>(&Bs[cur][k][64 + tn4]);
            unsigned long long am[4] = {aA.x, aA.y, aB.x, aB.y};
            unsigned long long bs[8];
            PACKF2(bs[0], b0.x, b0.x); PACKF2(bs[1], b0.y, b0.y);
            PACKF2(bs[2], b0.z, b0.z); PACKF2(bs[3], b0.w, b0.w);
            PACKF2(bs[4], b1.x, b1.x); PACKF2(bs[5], b1.y, b1.y);
            PACKF2(bs[6], b1.z, b1.z); PACKF2(bs[7], b1.w, b1.w);
#pragma unroll
            for (int mp = 0; mp < 4; ++mp)
#pragma unroll
                for (int n = 0; n < 8; ++n) FFMA2(acc[mp][n], am[mp], bs[n]);
        }

        if (kc + 1 < NKC) {
            stash(cur ^ 1);
            __syncthreads();
        }
    }

    // ---- epilogue ---------------------------------------------------------
    // unpack: m local index 0..7 = {tm4+0..3, 64+tm4+0..3}
    float dot[8][8];
#pragma unroll
    for (int mp = 0; mp < 4; ++mp)
#pragma unroll
        for (int n = 0; n < 8; ++n) {
            float lo, hi;
            UNPACKF2(lo, hi, acc[mp][n]);
            dot[2 * mp + 0][n] = lo;
            dot[2 * mp + 1][n] = hi;
        }

    const size_t BC = (size_t)B * (size_t)C;
    float* __restrict__ outCos = out;
    float* __restrict__ outMrg = out + BC;
    float* __restrict__ outIp  = out + 2 * BC;

    float invw[8];
#pragma unroll
    for (int j = 0; j < 8; ++j) {
        int gc = c0 + ((j < 4) ? (tn4 + j) : (64 + tn4 + j - 4));
        invw[j] = (gc < C) ? g_invnw[gc] : 0.f;
    }

    const bool full = (c0 + BN <= C);

#pragma unroll
    for (int mi = 0; mi < 8; ++mi) {
        int gm = m0 + ((mi < 4) ? (tm4 + mi) : (64 + tm4 + mi - 4));
        if (gm >= B) continue;
        float invf = g_invnf[gm];
        size_t ro = (size_t)gm * (size_t)C;
        if (full) {
            float4 ipv0 = make_float4(dot[mi][0], dot[mi][1], dot[mi][2], dot[mi][3]);
            float4 ipv1 = make_float4(dot[mi][4], dot[mi][5], dot[mi][6], dot[mi][7]);
            float4 cv0  = make_float4(ipv0.x * invf * invw[0], ipv0.y * invf * invw[1],
                                      ipv0.z * invf * invw[2], ipv0.w * invf * invw[3]);
            float4 cv1  = make_float4(ipv1.x * invf * invw[4], ipv1.y * invf * invw[5],
                                      ipv1.z * invf * invw[6], ipv1.w * invf * invw[7]);
            float4 mv0  = make_float4(K_SCALE * cv0.x, K_SCALE * cv0.y,
                                      K_SCALE * cv0.z, K_SCALE * cv0.w);
            float4 mv1  = make_float4(K_SCALE * cv1.x, K_SCALE * cv1.y,
                                      K_SCALE * cv1.z, K_SCALE * cv1.w);
            size_t o0 = ro + c0 + tn4;
            size_t o1 = ro + c0 + 64 + tn4;
            *reinterpret_cast<float4*>(outCos + o0) = cv0;
            *reinterpret_cast<float4*>(outCos + o1) = cv1;
            *reinterpret_cast<float4*>(outMrg + o0) = mv0;
            *reinterpret_cast<float4*>(outMrg + o1) = mv1;
            *reinterpret_cast<float4*>(outIp  + o0) = ipv0;
            *reinterpret_cast<float4*>(outIp  + o1) = ipv1;
        } else {
#pragma unroll
            for (int j = 0; j < 8; ++j) {
                int gc = c0 + ((j < 4) ? (tn4 + j) : (64 + tn4 + j - 4));
                if (gc < C) {
                    float ip = dot[mi][j];
                    float cs = ip * invf * invw[j];
                    outCos[ro + gc] = cs;
                    outMrg[ro + gc] = K_SCALE * cs;
                    outIp [ro + gc] = ip;
                }
            }
        }
    }
}

// ---------------------------------------------------------------------------
// Replace marginal_logits at the ground-truth column (256 elements).
// Label dtype: JAX with x64 disabled emits int32 despite the jnp.int64
// annotation in the reference -> read as int. Clamp defensively so a dtype
// surprise degrades to rel_err, never an illegal access.
// ---------------------------------------------------------------------------
__global__ void fix_gt_kernel(const int* __restrict__ label,
                              float* __restrict__ out, int B, int C) {
    int b = blockIdx.x * blockDim.x + threadIdx.x;
    if (b >= B) return;
    int c = label[b];
    c = max(0, min(c, C - 1));
    size_t BC = (size_t)B * (size_t)C;
    float cg = out[(size_t)b * C + c];                   // cos at gt
    float cl = fminf(fmaxf(cg, -1.f), 1.f);
    float val;
    if (cg > kTHRESH) {
        // cos(acos(cl) + m) = cl*cos(m) - sqrt(1-cl^2)*sin(m)
        float s = sqrtf(fmaxf(1.f - cl * cl, 0.f));
        val = cl * kCOS_M - s * kSIN_M;
    } else {
        val = cl - K_MARGIN * kSIN_M;                    // cos(acos(cl)) - m*sin(m)
    }
    out[BC + (size_t)b * C + c] = K_SCALE * val;
}

// ---------------------------------------------------------------------------
extern "C" void kernel_launch(void* const* d_in, const int* in_sizes, int n_in,
                              void* d_out, int out_size) {
    const float* feat = (const float*)d_in[0];
    const float* W    = (const float*)d_in[1];
    const int*   label = (const int*)d_in[2];
    const int D = 128;
    int B = in_sizes[0] / D;
    int C = in_sizes[1] / D;
    float* out = (float*)d_out;

    dim3 nb(32, 8);
    norm_kernel<<<(B + 7) / 8, nb>>>(feat, B, 0);
    norm_kernel<<<(C + 7) / 8, nb>>>(W, C, 1);   // also pre-warms W into L2

    dim3 grid((C + 127) / 128, (B + 127) / 128);
    arcface_gemm<<<grid, 256>>>(feat, W, out, B, C);

    fix_gt_kernel<<<(B + 255) / 256, 256>>>(label, out, B, C);
}